// round 2
// baseline (speedup 1.0000x reference)
#include <cuda_runtime.h>
#include <cuda_bf16.h>
#include <math.h>

// Problem constants
#define ES    8
#define DS    1024
#define HS    2048
#define DOUTS 1024
#define TS    8192
#define CAP   8192   // worst-case tokens per expert (duplicates merge)

// ---------------- scratch (device globals; allocations are banned) ----------
__device__ int   g_cnt[ES];
__device__ int   g_tok[ES * CAP];
__device__ float g_wt [ES * CAP];
__device__ int   g_slot0[TS];
__device__ int   g_slot1[TS];
__device__ float g_Hb[(size_t)ES * CAP * HS];    // h = silu(g)*u*w  (512 MB)
__device__ float g_O[(size_t)ES * CAP * DOUTS];  // down proj output (256 MB)

// ---------------- routing ----------------------------------------------------
__global__ void zero_cnt_kernel() {
    if (threadIdx.x < ES) g_cnt[threadIdx.x] = 0;
}

// NOTE: top_k_indices is int32 (JAX default int width), NOT int64.
__global__ void build_kernel(const int* __restrict__ idx,
                             const float* __restrict__ w) {
    int t = blockIdx.x * blockDim.x + threadIdx.x;
    if (t >= TS) return;
    int e0 = idx[2 * t];
    int e1 = idx[2 * t + 1];
    float w0 = w[2 * t];
    float w1 = w[2 * t + 1];
    // range guard (defensive; avoids wild atomics if dtype assumption shifts)
    if ((unsigned)e0 >= ES) e0 = 0;
    if ((unsigned)e1 >= ES) e1 = 0;
    if (e0 == e1) {
        int s = atomicAdd(&g_cnt[e0], 1);
        g_tok[e0 * CAP + s] = t;
        g_wt [e0 * CAP + s] = w0 + w1;
        g_slot0[t] = e0 * CAP + s;
        g_slot1[t] = -1;
    } else {
        int s0 = atomicAdd(&g_cnt[e0], 1);
        g_tok[e0 * CAP + s0] = t;
        g_wt [e0 * CAP + s0] = w0;
        int s1 = atomicAdd(&g_cnt[e1], 1);
        g_tok[e1 * CAP + s1] = t;
        g_wt [e1 * CAP + s1] = w1;
        g_slot0[t] = e0 * CAP + s0;
        g_slot1[t] = e1 * CAP + s1;
    }
}

// ---------------- fused gate+up GEMM -----------------------------------------
// For expert e, token tile of 128 gathered rows, N-tile of 64 H-columns:
//   g = X_tile @ Wg_e[n0:n0+64,:]^T ; u = X_tile @ Wu_e[...]^T
//   h = silu(g) * u * combine_weight  -> g_Hb
__global__ __launch_bounds__(256, 1)
void gateup_kernel(const float* __restrict__ X,
                   const float* __restrict__ Wg,
                   const float* __restrict__ Wu) {
    int e = blockIdx.z;
    int cnt = g_cnt[e];
    int m0 = blockIdx.x * 128;
    if (m0 >= cnt) return;
    int n0 = blockIdx.y * 64;

    __shared__ float As[8][128];
    __shared__ float Bg[8][64];
    __shared__ float Bu[8][64];

    int tid = threadIdx.x;

    // A loader: 128 rows x 8 k, one float4 per thread
    int rowA  = tid >> 1;
    int ksegA = (tid & 1) * 4;
    int slotA = m0 + rowA;
    int token = (slotA < cnt) ? g_tok[e * CAP + slotA] : 0;
    const float* Arow = X + (size_t)token * DS;

    // B loaders: threads 0..127 -> Wg panel, 128..255 -> Wu panel
    int rowB  = (tid & 127) >> 1;    // 0..63
    int ksegB = (tid & 1) * 4;
    bool doU = (tid >= 128);
    const float* Brow = (doU ? Wu : Wg) + ((size_t)e * HS + n0 + rowB) * DS;

    int tx = tid & 15;   // n micro (4 cols)
    int ty = tid >> 4;   // m micro (8 rows)

    float accG[8][4], accU[8][4];
#pragma unroll
    for (int i = 0; i < 8; i++)
#pragma unroll
        for (int j = 0; j < 4; j++) { accG[i][j] = 0.f; accU[i][j] = 0.f; }

    for (int k0 = 0; k0 < DS; k0 += 8) {
        float4 av = *(const float4*)(Arow + k0 + ksegA);
        float4 bv = *(const float4*)(Brow + k0 + ksegB);
        As[ksegA + 0][rowA] = av.x;
        As[ksegA + 1][rowA] = av.y;
        As[ksegA + 2][rowA] = av.z;
        As[ksegA + 3][rowA] = av.w;
        float (*Bsp)[64] = doU ? Bu : Bg;
        Bsp[ksegB + 0][rowB] = bv.x;
        Bsp[ksegB + 1][rowB] = bv.y;
        Bsp[ksegB + 2][rowB] = bv.z;
        Bsp[ksegB + 3][rowB] = bv.w;
        __syncthreads();
#pragma unroll
        for (int kk = 0; kk < 8; kk++) {
            float4 a0 = *(const float4*)&As[kk][ty * 8];
            float4 a1 = *(const float4*)&As[kk][ty * 8 + 4];
            float4 bg = *(const float4*)&Bg[kk][tx * 4];
            float4 bu = *(const float4*)&Bu[kk][tx * 4];
            float am[8] = {a0.x, a0.y, a0.z, a0.w, a1.x, a1.y, a1.z, a1.w};
            float bgn[4] = {bg.x, bg.y, bg.z, bg.w};
            float bun[4] = {bu.x, bu.y, bu.z, bu.w};
#pragma unroll
            for (int i = 0; i < 8; i++)
#pragma unroll
                for (int j = 0; j < 4; j++) {
                    accG[i][j] = fmaf(am[i], bgn[j], accG[i][j]);
                    accU[i][j] = fmaf(am[i], bun[j], accU[i][j]);
                }
        }
        __syncthreads();
    }

    int ecap = e * CAP;
#pragma unroll
    for (int mi = 0; mi < 8; mi++) {
        int slot = m0 + ty * 8 + mi;
        if (slot >= cnt) continue;
        float wv = g_wt[ecap + slot];
        float* hr = g_Hb + (size_t)(ecap + slot) * HS + n0 + tx * 4;
        float4 hv;
        float g0 = accG[mi][0], g1 = accG[mi][1], g2 = accG[mi][2], g3 = accG[mi][3];
        hv.x = (g0 / (1.0f + __expf(-g0))) * accU[mi][0] * wv;
        hv.y = (g1 / (1.0f + __expf(-g1))) * accU[mi][1] * wv;
        hv.z = (g2 / (1.0f + __expf(-g2))) * accU[mi][2] * wv;
        hv.w = (g3 / (1.0f + __expf(-g3))) * accU[mi][3] * wv;
        *(float4*)hr = hv;
    }
}

// ---------------- down GEMM: O = H @ Wd^T ------------------------------------
__global__ __launch_bounds__(256, 1)
void down_kernel(const float* __restrict__ Wd) {
    int e = blockIdx.z;
    int cnt = g_cnt[e];
    int m0 = blockIdx.x * 128;
    if (m0 >= cnt) return;
    int n0 = blockIdx.y * 128;

    const float* W = Wd + (size_t)e * DOUTS * HS;

    __shared__ float As[8][128];
    __shared__ float Bs[8][128];

    int tid  = threadIdx.x;
    int rowA = tid >> 1;
    int kseg = (tid & 1) * 4;

    const float* Arow = g_Hb + (size_t)(e * CAP + m0 + rowA) * HS;
    const float* Brow = W + (size_t)(n0 + rowA) * HS;

    int tx = tid & 15;
    int ty = tid >> 4;

    float acc[8][8];
#pragma unroll
    for (int i = 0; i < 8; i++)
#pragma unroll
        for (int j = 0; j < 8; j++) acc[i][j] = 0.f;

    for (int k0 = 0; k0 < HS; k0 += 8) {
        float4 av = *(const float4*)(Arow + k0 + kseg);
        float4 bv = *(const float4*)(Brow + k0 + kseg);
        As[kseg + 0][rowA] = av.x;
        As[kseg + 1][rowA] = av.y;
        As[kseg + 2][rowA] = av.z;
        As[kseg + 3][rowA] = av.w;
        Bs[kseg + 0][rowA] = bv.x;
        Bs[kseg + 1][rowA] = bv.y;
        Bs[kseg + 2][rowA] = bv.z;
        Bs[kseg + 3][rowA] = bv.w;
        __syncthreads();
#pragma unroll
        for (int kk = 0; kk < 8; kk++) {
            float4 a0 = *(const float4*)&As[kk][ty * 8];
            float4 a1 = *(const float4*)&As[kk][ty * 8 + 4];
            float4 b0 = *(const float4*)&Bs[kk][tx * 8];
            float4 b1 = *(const float4*)&Bs[kk][tx * 8 + 4];
            float am[8] = {a0.x, a0.y, a0.z, a0.w, a1.x, a1.y, a1.z, a1.w};
            float bn[8] = {b0.x, b0.y, b0.z, b0.w, b1.x, b1.y, b1.z, b1.w};
#pragma unroll
            for (int i = 0; i < 8; i++)
#pragma unroll
                for (int j = 0; j < 8; j++)
                    acc[i][j] = fmaf(am[i], bn[j], acc[i][j]);
        }
        __syncthreads();
    }

    int ecap = e * CAP;
#pragma unroll
    for (int mi = 0; mi < 8; mi++) {
        int slot = m0 + ty * 8 + mi;
        if (slot >= cnt) continue;
        float* orow = g_O + (size_t)(ecap + slot) * DOUTS + n0 + tx * 8;
        float4 v0 = {acc[mi][0], acc[mi][1], acc[mi][2], acc[mi][3]};
        float4 v1 = {acc[mi][4], acc[mi][5], acc[mi][6], acc[mi][7]};
        *(float4*)orow       = v0;
        *(float4*)(orow + 4) = v1;
    }
}

// ---------------- final combine ---------------------------------------------
__global__ void combine_kernel(float* __restrict__ out) {
    int i = blockIdx.x * blockDim.x + threadIdx.x;  // over TS*DOUTS/4
    if (i >= TS * (DOUTS / 4)) return;
    int t  = i / (DOUTS / 4);
    int d4 = i % (DOUTS / 4);
    const float4* O4 = (const float4*)g_O;
    float4 a = O4[(size_t)g_slot0[t] * (DOUTS / 4) + d4];
    int s1 = g_slot1[t];
    if (s1 >= 0) {
        float4 b = O4[(size_t)s1 * (DOUTS / 4) + d4];
        a.x += b.x; a.y += b.y; a.z += b.z; a.w += b.w;
    }
    ((float4*)out)[i] = a;
}

// ---------------- launch -----------------------------------------------------
extern "C" void kernel_launch(void* const* d_in, const int* in_sizes, int n_in,
                              void* d_out, int out_size) {
    const float* X   = (const float*)d_in[0];   // [T, D]
    const int*   idx = (const int*)d_in[1];     // [T, K] int32 (JAX default)
    const float* wts = (const float*)d_in[2];   // [T, K]
    const float* Wg  = (const float*)d_in[3];   // [E, H, D]
    const float* Wu  = (const float*)d_in[4];   // [E, H, D]
    const float* Wd  = (const float*)d_in[5];   // [E, DOUT, H]
    float* out = (float*)d_out;                 // [T, DOUT]

    zero_cnt_kernel<<<1, 32>>>();
    build_kernel<<<(TS + 255) / 256, 256>>>(idx, wts);

    dim3 gUp(CAP / 128, HS / 64, ES);           // 64 x 32 x 8 (early-exit on count)
    gateup_kernel<<<gUp, 256>>>(X, Wg, Wu);

    dim3 gDn(CAP / 128, DOUTS / 128, ES);       // 64 x 8 x 8
    down_kernel<<<gDn, 256>>>(Wd);

    combine_kernel<<<(TS * (DOUTS / 4) + 255) / 256, 256>>>(out);
}